// round 17
// baseline (speedup 1.0000x reference)
#include <cuda_runtime.h>
#include <cuda_bf16.h>
#include <math.h>
#include <stdint.h>

// Problem dims (fixed by the dataset)
#define NN 8192
#define DD 1024
#define HH 4096
#define KK 4096   // codebook

// ---------------- scratch (static __device__, allocation-free) ----------------
__device__ float g_hcat[(size_t)NN * 2 * HH];   // [8192, 8192]
__device__ float g_h2[(size_t)NN * HH];         // [8192, 4096] (reused for scores)
__device__ float g_h3[(size_t)NN * HH];         // [8192, 4096]
__device__ float g_z[(size_t)NN * DD];          // [8192, 1024]
__device__ float g_e2[KK];
__device__ int   g_idx[NN];

// ---------------- packed f32x2 helpers ----------------
__device__ __forceinline__ void fma2(unsigned long long& c,
                                     unsigned long long a,
                                     unsigned long long b) {
    asm("fma.rn.f32x2 %0, %1, %2, %0;" : "+l"(c) : "l"(a), "l"(b));
}
__device__ __forceinline__ float lo_f(unsigned long long v) {
    float lo, hi;
    asm("mov.b64 {%0, %1}, %2;" : "=f"(lo), "=f"(hi) : "l"(v));
    return lo;
}
__device__ __forceinline__ float hi_f(unsigned long long v) {
    float lo, hi;
    asm("mov.b64 {%0, %1}, %2;" : "=f"(lo), "=f"(hi) : "l"(v));
    return hi;
}

// ============================ FFMA2 GEMM (B pre-duplicated in smem) ===========
// C[m,n] = act( sum_k A[m,k]*B[n,k] + bias[n] ),  A:[M,K], B:[N,K] row-major.
// CTA tile 256x128, 256 threads, thread tile 16x8 held as 8 m-pairs x 8 cols.
// A pairs = adjacent m floats (direct 64-bit LDS lanes). B is stored in smem
// as duplicated (b,b) pairs, so B dup operands also load directly via LDS.128
// -> ZERO pack MOVs in the inner loop; fma pipe sees pure FFMA2.
// fma.rn.f32x2 = two independent IEEE fma.rn.f32 lanes; each output element
// keeps one accumulator with strictly ascending k -> bit-identical to rounds
// 1/7/9/10/13/14 (rel_err 6.29e-8). Fragment double-buffer hides LDS latency;
// register-staged smem double buffer with spread STS/LDG (round 10).
#define BM 256
#define BN 128
#define BK 16
#define TM 16
#define TN 8
#define A_STG (BK * BM)           // 4096 floats per A stage
#define B_STG (BK * 2 * BN)       // 4096 floats per B stage (duplicated)
#define GSMEM_BYTES ((2 * A_STG + 2 * B_STG) * 4)   // 65536

// ACT: 0=bias  1=fourier(bias+acc)  2=cat raw+fourier (ldc=2N)  3=score bias-2*acc
template <int ACT>
__global__ __launch_bounds__(256, 1)
void gemm_f2d(const float* __restrict__ A, const float* __restrict__ B,
              const float* __restrict__ bias, float* __restrict__ C,
              int M, int N, int K, int ldc)
{
    extern __shared__ float sm[];
    // layout: A stage0 | A stage1 | B stage0 | B stage1
    float* Asm[2] = { sm, sm + A_STG };
    float* Bsm[2] = { sm + 2 * A_STG, sm + 2 * A_STG + B_STG };

    const int tid  = threadIdx.x;
    const int lane = tid & 31;
    const int wid  = tid >> 5;
    const int ty = lane >> 3;           // 0..3  (row groups of 16)
    const int tx = lane & 7;            // 0..7  (col groups of 8)
    const int wm = (wid >> 1) * 64;     // 4 warp-rows
    const int wn = (wid & 1) * 64;      // 2 warp-cols
    const int m0 = blockIdx.y * BM;
    const int n0 = blockIdx.x * BN;

    // loader mapping: A: thread tid owns full row tid (16 floats)
    //                 B: 2 threads per row, 8 k's each
    const int blr = tid >> 1;
    const int blk = (tid & 1) * 8;
    const float* ag = A + (size_t)(m0 + tid) * K;
    const float* bg = B + (size_t)(n0 + blr) * K + blk;

    const int nk = K / BK;

    // ---- prologue: LDG chunk0 -> STS stage0 ; LDG chunk1 -> regs ----
    float4 a0, a1, a2, a3, b0, b1;
    a0 = *(const float4*)(ag);      a1 = *(const float4*)(ag + 4);
    a2 = *(const float4*)(ag + 8);  a3 = *(const float4*)(ag + 12);
    b0 = *(const float4*)(bg);      b1 = *(const float4*)(bg + 4);
    {
        float* As0 = Asm[0];
        float* Bs0 = Bsm[0];
        As0[ 0 * BM + tid] = a0.x; As0[ 1 * BM + tid] = a0.y;
        As0[ 2 * BM + tid] = a0.z; As0[ 3 * BM + tid] = a0.w;
        As0[ 4 * BM + tid] = a1.x; As0[ 5 * BM + tid] = a1.y;
        As0[ 6 * BM + tid] = a1.z; As0[ 7 * BM + tid] = a1.w;
        As0[ 8 * BM + tid] = a2.x; As0[ 9 * BM + tid] = a2.y;
        As0[10 * BM + tid] = a2.z; As0[11 * BM + tid] = a2.w;
        As0[12 * BM + tid] = a3.x; As0[13 * BM + tid] = a3.y;
        As0[14 * BM + tid] = a3.z; As0[15 * BM + tid] = a3.w;
        const int bp = 2 * blr;
        *(float2*)&Bs0[(blk + 0) * 2 * BN + bp] = make_float2(b0.x, b0.x);
        *(float2*)&Bs0[(blk + 1) * 2 * BN + bp] = make_float2(b0.y, b0.y);
        *(float2*)&Bs0[(blk + 2) * 2 * BN + bp] = make_float2(b0.z, b0.z);
        *(float2*)&Bs0[(blk + 3) * 2 * BN + bp] = make_float2(b0.w, b0.w);
        *(float2*)&Bs0[(blk + 4) * 2 * BN + bp] = make_float2(b1.x, b1.x);
        *(float2*)&Bs0[(blk + 5) * 2 * BN + bp] = make_float2(b1.y, b1.y);
        *(float2*)&Bs0[(blk + 6) * 2 * BN + bp] = make_float2(b1.z, b1.z);
        *(float2*)&Bs0[(blk + 7) * 2 * BN + bp] = make_float2(b1.w, b1.w);
    }
    if (nk > 1) {
        a0 = *(const float4*)(ag + BK);      a1 = *(const float4*)(ag + BK + 4);
        a2 = *(const float4*)(ag + BK + 8);  a3 = *(const float4*)(ag + BK + 12);
        b0 = *(const float4*)(bg + BK);      b1 = *(const float4*)(bg + BK + 4);
    }

    // acc pairs over M: acc2[p][j] = (acc[2p][j], acc[2p+1][j])
    unsigned long long acc2[TM / 2][TN];
#pragma unroll
    for (int p = 0; p < TM / 2; p++)
#pragma unroll
        for (int j = 0; j < TN; j++) acc2[p][j] = 0ull;

    for (int c = 0; c < nk; c++) {
        __syncthreads();   // STS(c) visible; stage (c+1)&1 free for writing

        const int s = (c + 1) & 1;                 // stage being filled
        const bool do_sts = (c + 1 < nk);
        const bool do_ldg = (c + 2 < nk);
        const float* an = ag + (size_t)(c + 2) * BK;   // LDG source (chunk c+2)
        const float* bn = bg + (size_t)(c + 2) * BK;
        float* Asw = Asm[s];
        float* Bsw = Bsm[s];

        const float* as = Asm[c & 1];
        const float* bs = Bsm[c & 1];
        const float* afrag = as + wm + ty * TM;
        const float* bfrag = bs + 2 * (wn + tx * TN);

        // ---- fragment double buffer: load kk=0 ----
        ulonglong2 au[2][2];
        ulonglong2 bd[2][2];
        au[0][0] = *(const ulonglong2*)(afrag);
        au[0][1] = *(const ulonglong2*)(afrag + 4);
        ulonglong2 au_hi0 = *(const ulonglong2*)(afrag + 8);
        ulonglong2 au_hi1 = *(const ulonglong2*)(afrag + 12);
        bd[0][0] = *(const ulonglong2*)(bfrag);
        bd[0][1] = *(const ulonglong2*)(bfrag + 4);
        ulonglong2 bd_hi0 = *(const ulonglong2*)(bfrag + 8);
        ulonglong2 bd_hi1 = *(const ulonglong2*)(bfrag + 12);
        ulonglong2 au_hi[2][2], bd_hi[2][2];
        au_hi[0][0] = au_hi0; au_hi[0][1] = au_hi1;
        bd_hi[0][0] = bd_hi0; bd_hi[0][1] = bd_hi1;

#pragma unroll
        for (int kk = 0; kk < BK; kk++) {
            const int cur = kk & 1;
            const int nxt = cur ^ 1;
            // prefetch kk+1 fragments (latency hidden under compute)
            if (kk + 1 < BK) {
                const float* ar = afrag + (kk + 1) * BM;
                const float* br = bfrag + (kk + 1) * 2 * BN;
                au[nxt][0]    = *(const ulonglong2*)(ar);
                au[nxt][1]    = *(const ulonglong2*)(ar + 4);
                au_hi[nxt][0] = *(const ulonglong2*)(ar + 8);
                au_hi[nxt][1] = *(const ulonglong2*)(ar + 12);
                bd[nxt][0]    = *(const ulonglong2*)(br);
                bd[nxt][1]    = *(const ulonglong2*)(br + 4);
                bd_hi[nxt][0] = *(const ulonglong2*)(br + 8);
                bd_hi[nxt][1] = *(const ulonglong2*)(br + 12);
            }

            // ---- compute kk: pure FFMA2, zero MOVs ----
            unsigned long long Ap[TM / 2];
            Ap[0] = au[cur][0].x;    Ap[1] = au[cur][0].y;
            Ap[2] = au[cur][1].x;    Ap[3] = au[cur][1].y;
            Ap[4] = au_hi[cur][0].x; Ap[5] = au_hi[cur][0].y;
            Ap[6] = au_hi[cur][1].x; Ap[7] = au_hi[cur][1].y;
            unsigned long long Bd[TN];
            Bd[0] = bd[cur][0].x;    Bd[1] = bd[cur][0].y;
            Bd[2] = bd[cur][1].x;    Bd[3] = bd[cur][1].y;
            Bd[4] = bd_hi[cur][0].x; Bd[5] = bd_hi[cur][0].y;
            Bd[6] = bd_hi[cur][1].x; Bd[7] = bd_hi[cur][1].y;
#pragma unroll
            for (int p = 0; p < TM / 2; p++)
#pragma unroll
                for (int j = 0; j < TN; j++)
                    fma2(acc2[p][j], Ap[p], Bd[j]);

            // ---- interleaved staging: retire one quad (STS then reload) ----
            if (kk == 1) {
                if (do_sts) {
                    Asw[0 * BM + tid] = a0.x; Asw[1 * BM + tid] = a0.y;
                    Asw[2 * BM + tid] = a0.z; Asw[3 * BM + tid] = a0.w;
                }
                if (do_ldg) a0 = *(const float4*)(an);
            } else if (kk == 3) {
                if (do_sts) {
                    Asw[4 * BM + tid] = a1.x; Asw[5 * BM + tid] = a1.y;
                    Asw[6 * BM + tid] = a1.z; Asw[7 * BM + tid] = a1.w;
                }
                if (do_ldg) a1 = *(const float4*)(an + 4);
            } else if (kk == 5) {
                if (do_sts) {
                    Asw[ 8 * BM + tid] = a2.x; Asw[ 9 * BM + tid] = a2.y;
                    Asw[10 * BM + tid] = a2.z; Asw[11 * BM + tid] = a2.w;
                }
                if (do_ldg) a2 = *(const float4*)(an + 8);
            } else if (kk == 7) {
                if (do_sts) {
                    Asw[12 * BM + tid] = a3.x; Asw[13 * BM + tid] = a3.y;
                    Asw[14 * BM + tid] = a3.z; Asw[15 * BM + tid] = a3.w;
                }
                if (do_ldg) a3 = *(const float4*)(an + 12);
            } else if (kk == 9) {
                if (do_sts) {
                    const int bp = 2 * blr;
                    *(float2*)&Bsw[(blk + 0) * 2 * BN + bp] = make_float2(b0.x, b0.x);
                    *(float2*)&Bsw[(blk + 1) * 2 * BN + bp] = make_float2(b0.y, b0.y);
                    *(float2*)&Bsw[(blk + 2) * 2 * BN + bp] = make_float2(b0.z, b0.z);
                    *(float2*)&Bsw[(blk + 3) * 2 * BN + bp] = make_float2(b0.w, b0.w);
                }
                if (do_ldg) b0 = *(const float4*)(bn);
            } else if (kk == 11) {
                if (do_sts) {
                    const int bp = 2 * blr;
                    *(float2*)&Bsw[(blk + 4) * 2 * BN + bp] = make_float2(b1.x, b1.x);
                    *(float2*)&Bsw[(blk + 5) * 2 * BN + bp] = make_float2(b1.y, b1.y);
                    *(float2*)&Bsw[(blk + 6) * 2 * BN + bp] = make_float2(b1.z, b1.z);
                    *(float2*)&Bsw[(blk + 7) * 2 * BN + bp] = make_float2(b1.w, b1.w);
                }
                if (do_ldg) b1 = *(const float4*)(bn + 4);
            }
        }
    }

    // ---- epilogue (identical expressions to rounds 1/7/9/10/13/14) ----
#pragma unroll
    for (int p = 0; p < TM / 2; p++) {
        const int me = m0 + wm + ty * TM + 2 * p;   // even row of the pair
        float* crow0 = C + (size_t)me * ldc;
        float* crow1 = C + (size_t)(me + 1) * ldc;
#pragma unroll
        for (int j = 0; j < TN; j++) {
            const int n = n0 + wn + tx * TN + j;
            const float s0 = lo_f(acc2[p][j]);   // row me
            const float s1 = hi_f(acc2[p][j]);   // row me+1
            if (ACT == 0) {
                crow0[n] = s0 + bias[n];
                crow1[n] = s1 + bias[n];
            } else if (ACT == 1) {
                const float v0 = s0 + bias[n];
                const float v1 = s1 + bias[n];
                crow0[n] = (n & 1) ? cosf(v0) : sinf(v0);
                crow1[n] = (n & 1) ? cosf(v1) : sinf(v1);
            } else if (ACT == 2) {
                const float v0 = s0 + bias[n];
                const float v1 = s1 + bias[n];
                crow0[n] = v0;
                crow1[n] = v1;
                crow0[N + n] = (n & 1) ? cosf(v0) : sinf(v0);
                crow1[N + n] = (n & 1) ? cosf(v1) : sinf(v1);
            } else { // 3: score
                crow0[n] = bias[n] - 2.0f * s0;
                crow1[n] = bias[n] - 2.0f * s1;
            }
        }
    }
}

// ---------------- e2[k] = ||emb[k]||^2 ----------------
__global__ void e2_kernel(const float* __restrict__ emb, float* __restrict__ e2)
{
    __shared__ float red[256];
    const int k = blockIdx.x;
    const float* row = emb + (size_t)k * DD;
    float s = 0.f;
    for (int d = threadIdx.x; d < DD; d += 256) { float v = row[d]; s += v * v; }
    red[threadIdx.x] = s;
    __syncthreads();
    for (int o = 128; o > 0; o >>= 1) {
        if (threadIdx.x < o) red[threadIdx.x] += red[threadIdx.x + o];
        __syncthreads();
    }
    if (threadIdx.x == 0) e2[k] = red[0];
}

// ---------------- per-row argmin over K scores (first-index tie-break) -------
__global__ void argmin_kernel(const float* __restrict__ scores, int* __restrict__ idx)
{
    __shared__ float bv[256];
    __shared__ int   bi[256];
    const int n = blockIdx.x;
    const float* row = scores + (size_t)n * KK;
    float best = 3.4e38f;
    int besti = 0;
    for (int k = threadIdx.x; k < KK; k += 256) {
        float v = row[k];
        if (v < best) { best = v; besti = k; }
    }
    bv[threadIdx.x] = best;
    bi[threadIdx.x] = besti;
    __syncthreads();
    for (int o = 128; o > 0; o >>= 1) {
        if (threadIdx.x < o) {
            float vo = bv[threadIdx.x + o];
            int   io = bi[threadIdx.x + o];
            if (vo < bv[threadIdx.x] ||
                (vo == bv[threadIdx.x] && io < bi[threadIdx.x])) {
                bv[threadIdx.x] = vo; bi[threadIdx.x] = io;
            }
        }
        __syncthreads();
    }
    if (threadIdx.x == 0) idx[n] = bi[0];
}

// ---------------- mueller hash (numpy int64 wraparound semantics) ------------
__device__ __forceinline__ long long mueller_hash(long long x)
{
    const unsigned long long C = 73244475ull;
    x = (long long)((unsigned long long)((x >> 16) ^ x) * C);
    x = (long long)((unsigned long long)((x >> 16) ^ x) * C);
    return (x >> 16) ^ x;
}

// ---------------- quantize: out[n] = sum_{i=1..3} emb[hash(idx+i*K)&(K-1)]/3 --
__global__ void quant_kernel(const float* __restrict__ emb,
                             const int* __restrict__ idx,
                             float* __restrict__ out)
{
    const int n = blockIdx.x;
    const long long id = (long long)idx[n];
    int s0 = (int)(mueller_hash(id + 1LL * KK) & (long long)(KK - 1));
    int s1 = (int)(mueller_hash(id + 2LL * KK) & (long long)(KK - 1));
    int s2 = (int)(mueller_hash(id + 3LL * KK) & (long long)(KK - 1));
    const float4* e0 = (const float4*)(emb + (size_t)s0 * DD);
    const float4* e1 = (const float4*)(emb + (size_t)s1 * DD);
    const float4* e2p = (const float4*)(emb + (size_t)s2 * DD);
    float4* o = (float4*)(out + (size_t)n * DD);
    const int d = threadIdx.x;
    float4 a = e0[d], b = e1[d], c = e2p[d];
    float4 r;
    r.x = (a.x / 3.0f + b.x / 3.0f) + c.x / 3.0f;
    r.y = (a.y / 3.0f + b.y / 3.0f) + c.y / 3.0f;
    r.z = (a.z / 3.0f + b.z / 3.0f) + c.z / 3.0f;
    r.w = (a.w / 3.0f + b.w / 3.0f) + c.w / 3.0f;
    o[d] = r;
}

// ---------------- host launcher ----------------
extern "C" void kernel_launch(void* const* d_in, const int* in_sizes, int n_in,
                              void* d_out, int out_size)
{
    const float* x   = (const float*)d_in[0];
    const float* w1  = (const float*)d_in[1];
    const float* b1  = (const float*)d_in[2];
    const float* w2  = (const float*)d_in[3];
    const float* b2  = (const float*)d_in[4];
    const float* w3  = (const float*)d_in[5];
    const float* b3  = (const float*)d_in[6];
    const float* w4  = (const float*)d_in[7];
    const float* b4  = (const float*)d_in[8];
    const float* emb = (const float*)d_in[9];
    float* out = (float*)d_out;

    float *hcat, *h2, *h3, *z, *e2d;
    int* idx;
    cudaGetSymbolAddress((void**)&hcat, g_hcat);
    cudaGetSymbolAddress((void**)&h2,   g_h2);
    cudaGetSymbolAddress((void**)&h3,   g_h3);
    cudaGetSymbolAddress((void**)&z,    g_z);
    cudaGetSymbolAddress((void**)&e2d,  g_e2);
    cudaGetSymbolAddress((void**)&idx,  g_idx);

    cudaFuncSetAttribute(gemm_f2d<0>, cudaFuncAttributeMaxDynamicSharedMemorySize, GSMEM_BYTES);
    cudaFuncSetAttribute(gemm_f2d<1>, cudaFuncAttributeMaxDynamicSharedMemorySize, GSMEM_BYTES);
    cudaFuncSetAttribute(gemm_f2d<2>, cudaFuncAttributeMaxDynamicSharedMemorySize, GSMEM_BYTES);
    cudaFuncSetAttribute(gemm_f2d<3>, cudaFuncAttributeMaxDynamicSharedMemorySize, GSMEM_BYTES);

    e2_kernel<<<KK, 256>>>(emb, e2d);

    // G1: hcat = [h1, fourier(h1)], h1 = x @ w1.T + b1
    gemm_f2d<2><<<dim3(HH / BN, NN / BM), 256, GSMEM_BYTES>>>(
        x, w1, b1, hcat, NN, HH, DD, 2 * HH);
    // G2: h2 = fourier(hcat @ w2.T + b2)
    gemm_f2d<1><<<dim3(HH / BN, NN / BM), 256, GSMEM_BYTES>>>(
        hcat, w2, b2, h2, NN, HH, 2 * HH, HH);
    // G3: h3 = fourier(h2 @ w3.T + b3)
    gemm_f2d<1><<<dim3(HH / BN, NN / BM), 256, GSMEM_BYTES>>>(
        h2, w3, b3, h3, NN, HH, HH, HH);
    // G4: z = h3 @ w4.T + b4
    gemm_f2d<0><<<dim3(DD / BN, NN / BM), 256, GSMEM_BYTES>>>(
        h3, w4, b4, z, NN, DD, HH, DD);
    // G5: scores = e2[k] - 2 * z @ emb.T  (reuse h2)
    gemm_f2d<3><<<dim3(KK / BN, NN / BM), 256, GSMEM_BYTES>>>(
        z, emb, e2d, h2, NN, KK, DD, KK);

    argmin_kernel<<<NN, 256>>>(h2, idx);
    quant_kernel<<<NN, 256>>>(emb, idx, out);
}